// round 13
// baseline (speedup 1.0000x reference)
#include <cuda_runtime.h>
#include <cstdint>

#define N_NODES_MAX 250000

// Scratch (device globals — zero-initialized at module load; no allocation allowed)
__device__ float  g_deg  [N_NODES_MAX];      // self-resetting: always 0 on kernel_launch entry
__device__ float  g_dinv [N_NODES_MAX];
__device__ float4 g_xsr  [N_NODES_MAX * 2];  // 32B/node record: [ch0..3][ch4,pad,pad,pad]
__device__ float4 g_agg1 [N_NODES_MAX * 2];  // layer-1 aggregation, same layout
__device__ float4 g_xs2  [N_NODES_MAX];      // layer-2 scaled features (16B/node)

__device__ __forceinline__ void red_add_v4(float4* addr, float4 v) {
    unsigned long long ga = __cvta_generic_to_global(addr);
    asm volatile("red.global.add.v4.f32 [%0], {%1,%2,%3,%4};"
                 :: "l"(ga), "f"(v.x), "f"(v.y), "f"(v.z), "f"(v.w)
                 : "memory");
}
__device__ __forceinline__ void red_add_f32(float* addr, float v) {
    unsigned long long ga = __cvta_generic_to_global(addr);
    asm volatile("red.global.add.f32 [%0], %1;" :: "l"(ga), "f"(v) : "memory");
}
__device__ __forceinline__ void pdl_trigger() {
    asm volatile("griddepcontrol.launch_dependents;");
}
__device__ __forceinline__ void pdl_wait() {
    asm volatile("griddepcontrol.wait;" ::: "memory");
}

// ---------------- kernels ----------------

// 8 edges per thread via 2x int4. Trigger at end.
__global__ void __launch_bounds__(32) k_deg_count(const int4* __restrict__ dst4, int e4) {
    int i = (blockIdx.x * blockDim.x + threadIdx.x) * 2;
    if (i < e4) {
        int4 d0 = dst4[i];
        atomicAdd(&g_deg[d0.x], 1.0f);
        atomicAdd(&g_deg[d0.y], 1.0f);
        atomicAdd(&g_deg[d0.z], 1.0f);
        atomicAdd(&g_deg[d0.w], 1.0f);
        if (i + 1 < e4) {
            int4 d1 = dst4[i + 1];
            atomicAdd(&g_deg[d1.x], 1.0f);
            atomicAdd(&g_deg[d1.y], 1.0f);
            atomicAdd(&g_deg[d1.z], 1.0f);
            atomicAdd(&g_deg[d1.w], 1.0f);
        }
    }
    pdl_trigger();
}
__global__ void __launch_bounds__(32) k_deg_scalar(const int* __restrict__ dst, int start, int e) {
    int i = start + blockIdx.x * blockDim.x + threadIdx.x;
    if (i < e) atomicAdd(&g_deg[dst[i]], 1.0f);
    pdl_trigger();
}

// dinv = rsqrt(deg+1); xsr = x*dinv; agg1 init = xsr (self loop); reset deg
__global__ void __launch_bounds__(128) k_node1(const float* __restrict__ x, int n) {
    pdl_trigger();
    int i = blockIdx.x * blockDim.x + threadIdx.x;
    if (i >= n) return;
    float x0 = x[i * 5 + 0], x1 = x[i * 5 + 1], x2 = x[i * 5 + 2],
          x3 = x[i * 5 + 3], x4 = x[i * 5 + 4];
    pdl_wait();   // deg counts complete
    float dinv = rsqrtf(g_deg[i] + 1.0f);   // +1 = self-loop
    g_deg[i] = 0.f;                          // reset for next graph replay
    g_dinv[i] = dinv;
    float4 a = make_float4(x0 * dinv, x1 * dinv, x2 * dinv, x3 * dinv);
    float  b = x4 * dinv;
    g_xsr [i * 2]       = a;
    g_xsr [i * 2 + 1].x = b;
    g_agg1[i * 2]       = a;
    g_agg1[i * 2 + 1].x = b;
}

// layer-1 aggregation; 4 edges/thread, int4 idx. Trigger at end.
__global__ void __launch_bounds__(32) k_edge1(const int4* __restrict__ src4,
                                              const int4* __restrict__ dst4, int e4) {
    int i = blockIdx.x * blockDim.x + threadIdx.x;
    if (i < e4) {
        int4 s = src4[i];
        int4 d = dst4[i];
        pdl_wait();   // g_xsr / g_agg1 ready
        float4 a0 = __ldg(&g_xsr[s.x * 2]);
        float4 a1 = __ldg(&g_xsr[s.y * 2]);
        float4 a2 = __ldg(&g_xsr[s.z * 2]);
        float4 a3 = __ldg(&g_xsr[s.w * 2]);
        float  b0 = __ldg(&g_xsr[s.x * 2 + 1].x);   // same 32B sector as a0 (L1 hit)
        float  b1 = __ldg(&g_xsr[s.y * 2 + 1].x);
        float  b2 = __ldg(&g_xsr[s.z * 2 + 1].x);
        float  b3 = __ldg(&g_xsr[s.w * 2 + 1].x);
        red_add_v4 (&g_agg1[d.x * 2], a0);
        red_add_f32(&g_agg1[d.x * 2 + 1].x, b0);
        red_add_v4 (&g_agg1[d.y * 2], a1);
        red_add_f32(&g_agg1[d.y * 2 + 1].x, b1);
        red_add_v4 (&g_agg1[d.z * 2], a2);
        red_add_f32(&g_agg1[d.z * 2 + 1].x, b2);
        red_add_v4 (&g_agg1[d.w * 2], a3);
        red_add_f32(&g_agg1[d.w * 2 + 1].x, b3);
    }
    pdl_trigger();
}
__global__ void __launch_bounds__(32) k_edge1_scalar(const int* __restrict__ src,
                                                     const int* __restrict__ dst, int start, int e) {
    int i = start + blockIdx.x * blockDim.x + threadIdx.x;
    if (i < e) {
        int s = src[i], d = dst[i];
        pdl_wait();
        float4 a = g_xsr[s * 2];
        float  b = g_xsr[s * 2 + 1].x;
        red_add_v4 (&g_agg1[d * 2], a);
        red_add_f32(&g_agg1[d * 2 + 1].x, b);
    }
    pdl_trigger();
}

// h = relu(dinv*(agg1raw @ W1) + b1); xs2 = (h @ W2)*dinv; out init = xs2 (self loop)
// Weights staged in shared memory (one pass of LDG per block, LDS broadcast after).
__global__ void __launch_bounds__(128) k_node2(const float* __restrict__ W1,
                                               const float* __restrict__ b1,
                                               const float* __restrict__ W2,
                                               float4* __restrict__ out, int n) {
    pdl_trigger();
    __shared__ float sW1[80], sb1[16], sW2[64];
    int t = threadIdx.x;
    if (t < 80)  sW1[t] = W1[t];
    if (t >= 80 && t < 96)  sb1[t - 80] = b1[t - 80];
    if (t >= 96 && t < 128) sW2[t - 96] = W2[t - 96];
    if (t < 32)  sW2[32 + t] = W2[32 + t];   // second half of W2 (64 floats total)
    __syncthreads();
    int i = blockIdx.x * blockDim.x + t;
    if (i >= n) return;
    pdl_wait();   // agg1 complete
    float dinv = g_dinv[i];
    float4 a  = g_agg1[i * 2];
    float  b5 = g_agg1[i * 2 + 1].x;
    float xa[5] = {a.x, a.y, a.z, a.w, b5};
    float h[16];
#pragma unroll
    for (int j = 0; j < 16; j++) {
        float acc = 0.f;
#pragma unroll
        for (int k = 0; k < 5; k++) acc = fmaf(xa[k], sW1[k * 16 + j], acc);
        h[j] = fmaxf(fmaf(dinv, acc, sb1[j]), 0.f);
    }
    float4 v;
    float* vp = &v.x;
#pragma unroll
    for (int c = 0; c < 4; c++) {
        float acc = 0.f;
#pragma unroll
        for (int j = 0; j < 16; j++) acc = fmaf(h[j], sW2[j * 4 + c], acc);
        vp[c] = acc * dinv;
    }
    g_xs2[i] = v;
    out[i]   = v;
}

// layer-2 aggregation; 4 edges/thread, int4 idx. Trigger at end.
__global__ void __launch_bounds__(32) k_edge2(const int4* __restrict__ src4,
                                              const int4* __restrict__ dst4,
                                              float4* __restrict__ out, int e4) {
    int i = blockIdx.x * blockDim.x + threadIdx.x;
    if (i < e4) {
        int4 s = src4[i];
        int4 d = dst4[i];
        pdl_wait();   // g_xs2 / out init complete
        float4 v0 = __ldg(&g_xs2[s.x]);
        float4 v1 = __ldg(&g_xs2[s.y]);
        float4 v2 = __ldg(&g_xs2[s.z]);
        float4 v3 = __ldg(&g_xs2[s.w]);
        red_add_v4(&out[d.x], v0);
        red_add_v4(&out[d.y], v1);
        red_add_v4(&out[d.z], v2);
        red_add_v4(&out[d.w], v3);
    }
    pdl_trigger();
}
__global__ void __launch_bounds__(32) k_edge2_scalar(const int* __restrict__ src,
                                                     const int* __restrict__ dst,
                                                     float4* __restrict__ out, int start, int e) {
    int i = start + blockIdx.x * blockDim.x + threadIdx.x;
    if (i < e) {
        int s = src[i], d = dst[i];
        pdl_wait();
        red_add_v4(&out[d], g_xs2[s]);
    }
    pdl_trigger();
}

__global__ void __launch_bounds__(128) k_node3(const float* __restrict__ b2,
                                               float4* __restrict__ out, int n) {
    int i = blockIdx.x * blockDim.x + threadIdx.x;
    if (i >= n) return;
    float c0 = b2[0], c1 = b2[1], c2 = b2[2], c3 = b2[3];
    float dinv = g_dinv[i];     // written by node1, long complete
    pdl_wait();                 // edge2 REDs complete
    float4 v = out[i];
    v.x = fmaxf(fmaf(dinv, v.x, c0), 0.f);
    v.y = fmaxf(fmaf(dinv, v.y, c1), 0.f);
    v.z = fmaxf(fmaf(dinv, v.z, c2), 0.f);
    v.w = fmaxf(fmaf(dinv, v.w, c3), 0.f);
    out[i] = v;
}

// ---------------- launch ----------------

static void launch_k(const void* fn, int grid, int block, void** args, bool pdl) {
    cudaLaunchConfig_t cfg = {};
    cfg.gridDim  = dim3((unsigned)grid, 1, 1);
    cfg.blockDim = dim3((unsigned)block, 1, 1);
    cfg.stream   = 0;
    cudaLaunchAttribute attr;
    attr.id = cudaLaunchAttributeProgrammaticStreamSerialization;
    attr.val.programmaticStreamSerializationAllowed = 1;
    if (pdl) { cfg.attrs = &attr; cfg.numAttrs = 1; }
    cudaLaunchKernelExC(&cfg, fn, args);
}

extern "C" void kernel_launch(void* const* d_in, const int* in_sizes, int n_in,
                              void* d_out, int out_size) {
    const float* x  = (const float*)d_in[0];   // [N,5]
    const int*   ei = (const int*)d_in[1];     // [2,E] int32
    const float* W1 = (const float*)d_in[2];   // [5,16]
    const float* b1 = (const float*)d_in[3];   // [16]
    const float* W2 = (const float*)d_in[4];   // [16,4]
    const float* b2 = (const float*)d_in[5];   // [4]

    int n = in_sizes[0] / 5;
    int e = in_sizes[1] / 2;
    const int* src = ei;
    const int* dst = ei + e;

    float4* out = (float4*)d_out;

    const int BN = 128;   // node kernels
    const int BE = 32;    // edge kernels (single-warp CTAs: minimal queue burst)
    int gn = (n + BN - 1) / BN;

    bool vec4 = ((e & 3) == 0) && ((((uintptr_t)dst) & 15) == 0) && ((((uintptr_t)src) & 15) == 0);
    int e4   = vec4 ? e / 4 : 0;
    int ge4  = (e4 + BE - 1) / BE;
    int gd   = ((e4 + 1) / 2 + BE - 1) / BE;
    int tail = e4 * 4;
    int gts  = (e - tail + BE - 1) / BE;

    const int4* src4 = (const int4*)src;
    const int4* dst4 = (const int4*)dst;

    if (vec4) {
        void* a[] = {(void*)&dst4, (void*)&e4};
        launch_k((const void*)k_deg_count, gd, BE, a, false);
    }
    if (tail < e) {
        void* a[] = {(void*)&dst, (void*)&tail, (void*)&e};
        launch_k((const void*)k_deg_scalar, gts, BE, a, vec4);
    }
    {   void* a[] = {(void*)&x, (void*)&n};
        launch_k((const void*)k_node1, gn, BN, a, true); }
    if (vec4) {
        void* a[] = {(void*)&src4, (void*)&dst4, (void*)&e4};
        launch_k((const void*)k_edge1, ge4, BE, a, true);
    }
    if (tail < e) {
        void* a[] = {(void*)&src, (void*)&dst, (void*)&tail, (void*)&e};
        launch_k((const void*)k_edge1_scalar, gts, BE, a, true);
    }
    {   void* a[] = {(void*)&W1, (void*)&b1, (void*)&W2, (void*)&out, (void*)&n};
        launch_k((const void*)k_node2, gn, BN, a, true); }
    if (vec4) {
        void* a[] = {(void*)&src4, (void*)&dst4, (void*)&out, (void*)&e4};
        launch_k((const void*)k_edge2, ge4, BE, a, true);
    }
    if (tail < e) {
        void* a[] = {(void*)&src, (void*)&dst, (void*)&out, (void*)&tail, (void*)&e};
        launch_k((const void*)k_edge2_scalar, gts, BE, a, true);
    }
    {   void* a[] = {(void*)&b2, (void*)&out, (void*)&n};
        launch_k((const void*)k_node3, gn, BN, a, true); }
}

// round 14
// speedup vs baseline: 1.0105x; 1.0105x over previous
#include <cuda_runtime.h>
#include <cstdint>

#define N_NODES_MAX 250000

// Scratch (device globals — zero-initialized at module load; no allocation allowed)
__device__ float  g_deg  [N_NODES_MAX];      // self-resetting: always 0 on kernel_launch entry
__device__ float  g_dinv [N_NODES_MAX];
__device__ float4 g_xsr  [N_NODES_MAX * 2];  // 32B/node record: [ch0..3][ch4,pad,pad,pad]
__device__ float4 g_agg1 [N_NODES_MAX * 2];  // layer-1 aggregation, same layout
__device__ float4 g_xs2  [N_NODES_MAX];      // layer-2 scaled features (16B/node)

__device__ __forceinline__ void red_add_v4(float4* addr, float4 v) {
    unsigned long long ga = __cvta_generic_to_global(addr);
    asm volatile("red.global.add.v4.f32 [%0], {%1,%2,%3,%4};"
                 :: "l"(ga), "f"(v.x), "f"(v.y), "f"(v.z), "f"(v.w)
                 : "memory");
}
__device__ __forceinline__ void red_add_f32(float* addr, float v) {
    unsigned long long ga = __cvta_generic_to_global(addr);
    asm volatile("red.global.add.f32 [%0], %1;" :: "l"(ga), "f"(v) : "memory");
}
__device__ __forceinline__ void pdl_trigger() {
    asm volatile("griddepcontrol.launch_dependents;");
}
__device__ __forceinline__ void pdl_wait() {
    asm volatile("griddepcontrol.wait;" ::: "memory");
}

// ---------------- kernels ----------------

// 8 edges per thread via 2x int4. Trigger at end.
__global__ void __launch_bounds__(64) k_deg_count(const int4* __restrict__ dst4, int e4) {
    int i = (blockIdx.x * blockDim.x + threadIdx.x) * 2;
    if (i < e4) {
        int4 d0 = dst4[i];
        atomicAdd(&g_deg[d0.x], 1.0f);
        atomicAdd(&g_deg[d0.y], 1.0f);
        atomicAdd(&g_deg[d0.z], 1.0f);
        atomicAdd(&g_deg[d0.w], 1.0f);
        if (i + 1 < e4) {
            int4 d1 = dst4[i + 1];
            atomicAdd(&g_deg[d1.x], 1.0f);
            atomicAdd(&g_deg[d1.y], 1.0f);
            atomicAdd(&g_deg[d1.z], 1.0f);
            atomicAdd(&g_deg[d1.w], 1.0f);
        }
    }
    pdl_trigger();
}
__global__ void __launch_bounds__(64) k_deg_scalar(const int* __restrict__ dst, int start, int e) {
    int i = start + blockIdx.x * blockDim.x + threadIdx.x;
    if (i < e) atomicAdd(&g_deg[dst[i]], 1.0f);
    pdl_trigger();
}

// dinv = rsqrt(deg+1); xsr = x*dinv; agg1 init = xsr (self loop); reset deg
__global__ void __launch_bounds__(256) k_node1(const float* __restrict__ x, int n) {
    pdl_trigger();
    int i = blockIdx.x * blockDim.x + threadIdx.x;
    if (i >= n) return;
    float x0 = x[i * 5 + 0], x1 = x[i * 5 + 1], x2 = x[i * 5 + 2],
          x3 = x[i * 5 + 3], x4 = x[i * 5 + 4];
    pdl_wait();   // deg counts complete
    float dinv = rsqrtf(g_deg[i] + 1.0f);   // +1 = self-loop
    g_deg[i] = 0.f;                          // reset for next graph replay
    g_dinv[i] = dinv;
    float4 a = make_float4(x0 * dinv, x1 * dinv, x2 * dinv, x3 * dinv);
    float  b = x4 * dinv;
    g_xsr [i * 2]       = a;
    g_xsr [i * 2 + 1].x = b;
    g_agg1[i * 2]       = a;
    g_agg1[i * 2 + 1].x = b;
}

// layer-1 aggregation; 4 edges/thread, int4 idx. Trigger at end.
__global__ void __launch_bounds__(64) k_edge1(const int4* __restrict__ src4,
                                              const int4* __restrict__ dst4, int e4) {
    int i = blockIdx.x * blockDim.x + threadIdx.x;
    if (i < e4) {
        int4 s = src4[i];
        int4 d = dst4[i];
        pdl_wait();   // g_xsr / g_agg1 ready
        float4 a0 = __ldg(&g_xsr[s.x * 2]);
        float4 a1 = __ldg(&g_xsr[s.y * 2]);
        float4 a2 = __ldg(&g_xsr[s.z * 2]);
        float4 a3 = __ldg(&g_xsr[s.w * 2]);
        float  b0 = __ldg(&g_xsr[s.x * 2 + 1].x);   // same 32B sector as a0 (L1 hit)
        float  b1 = __ldg(&g_xsr[s.y * 2 + 1].x);
        float  b2 = __ldg(&g_xsr[s.z * 2 + 1].x);
        float  b3 = __ldg(&g_xsr[s.w * 2 + 1].x);
        red_add_v4 (&g_agg1[d.x * 2], a0);
        red_add_f32(&g_agg1[d.x * 2 + 1].x, b0);
        red_add_v4 (&g_agg1[d.y * 2], a1);
        red_add_f32(&g_agg1[d.y * 2 + 1].x, b1);
        red_add_v4 (&g_agg1[d.z * 2], a2);
        red_add_f32(&g_agg1[d.z * 2 + 1].x, b2);
        red_add_v4 (&g_agg1[d.w * 2], a3);
        red_add_f32(&g_agg1[d.w * 2 + 1].x, b3);
    }
    pdl_trigger();
}
__global__ void __launch_bounds__(64) k_edge1_scalar(const int* __restrict__ src,
                                                     const int* __restrict__ dst, int start, int e) {
    int i = start + blockIdx.x * blockDim.x + threadIdx.x;
    if (i < e) {
        int s = src[i], d = dst[i];
        pdl_wait();
        float4 a = g_xsr[s * 2];
        float  b = g_xsr[s * 2 + 1].x;
        red_add_v4 (&g_agg1[d * 2], a);
        red_add_f32(&g_agg1[d * 2 + 1].x, b);
    }
    pdl_trigger();
}

// h = relu(dinv*(agg1raw @ W1) + b1); xs2 = (h @ W2)*dinv; out init = xs2 (self loop)
// Weights staged in shared memory (one pass of LDG per block, LDS broadcast after).
__global__ void __launch_bounds__(256) k_node2(const float* __restrict__ W1,
                                               const float* __restrict__ b1,
                                               const float* __restrict__ W2,
                                               float4* __restrict__ out, int n) {
    pdl_trigger();
    __shared__ float sW1[80], sb1[16], sW2[64];
    int t = threadIdx.x;
    if (t < 80)  sW1[t] = W1[t];
    if (t >= 80 && t < 96)  sb1[t - 80] = b1[t - 80];
    if (t >= 96 && t < 160) sW2[t - 96] = W2[t - 96];
    __syncthreads();
    int i = blockIdx.x * blockDim.x + t;
    if (i >= n) return;
    pdl_wait();   // agg1 complete
    float dinv = g_dinv[i];
    float4 a  = g_agg1[i * 2];
    float  b5 = g_agg1[i * 2 + 1].x;
    float xa[5] = {a.x, a.y, a.z, a.w, b5};
    float h[16];
#pragma unroll
    for (int j = 0; j < 16; j++) {
        float acc = 0.f;
#pragma unroll
        for (int k = 0; k < 5; k++) acc = fmaf(xa[k], sW1[k * 16 + j], acc);
        h[j] = fmaxf(fmaf(dinv, acc, sb1[j]), 0.f);
    }
    float4 v;
    float* vp = &v.x;
#pragma unroll
    for (int c = 0; c < 4; c++) {
        float acc = 0.f;
#pragma unroll
        for (int j = 0; j < 16; j++) acc = fmaf(h[j], sW2[j * 4 + c], acc);
        vp[c] = acc * dinv;
    }
    g_xs2[i] = v;
    out[i]   = v;
}

// layer-2 aggregation; 4 edges/thread, int4 idx. Trigger at end.
__global__ void __launch_bounds__(64) k_edge2(const int4* __restrict__ src4,
                                              const int4* __restrict__ dst4,
                                              float4* __restrict__ out, int e4) {
    int i = blockIdx.x * blockDim.x + threadIdx.x;
    if (i < e4) {
        int4 s = src4[i];
        int4 d = dst4[i];
        pdl_wait();   // g_xs2 / out init complete
        float4 v0 = __ldg(&g_xs2[s.x]);
        float4 v1 = __ldg(&g_xs2[s.y]);
        float4 v2 = __ldg(&g_xs2[s.z]);
        float4 v3 = __ldg(&g_xs2[s.w]);
        red_add_v4(&out[d.x], v0);
        red_add_v4(&out[d.y], v1);
        red_add_v4(&out[d.z], v2);
        red_add_v4(&out[d.w], v3);
    }
    pdl_trigger();
}
__global__ void __launch_bounds__(64) k_edge2_scalar(const int* __restrict__ src,
                                                     const int* __restrict__ dst,
                                                     float4* __restrict__ out, int start, int e) {
    int i = start + blockIdx.x * blockDim.x + threadIdx.x;
    if (i < e) {
        int s = src[i], d = dst[i];
        pdl_wait();
        red_add_v4(&out[d], g_xs2[s]);
    }
    pdl_trigger();
}

__global__ void __launch_bounds__(256) k_node3(const float* __restrict__ b2,
                                               float4* __restrict__ out, int n) {
    int i = blockIdx.x * blockDim.x + threadIdx.x;
    if (i >= n) return;
    float c0 = b2[0], c1 = b2[1], c2 = b2[2], c3 = b2[3];
    float dinv = g_dinv[i];     // written by node1, long complete
    pdl_wait();                 // edge2 REDs complete
    float4 v = out[i];
    v.x = fmaxf(fmaf(dinv, v.x, c0), 0.f);
    v.y = fmaxf(fmaf(dinv, v.y, c1), 0.f);
    v.z = fmaxf(fmaf(dinv, v.z, c2), 0.f);
    v.w = fmaxf(fmaf(dinv, v.w, c3), 0.f);
    out[i] = v;
}

// ---------------- launch ----------------

static void launch_k(const void* fn, int grid, int block, void** args, bool pdl) {
    cudaLaunchConfig_t cfg = {};
    cfg.gridDim  = dim3((unsigned)grid, 1, 1);
    cfg.blockDim = dim3((unsigned)block, 1, 1);
    cfg.stream   = 0;
    cudaLaunchAttribute attr;
    attr.id = cudaLaunchAttributeProgrammaticStreamSerialization;
    attr.val.programmaticStreamSerializationAllowed = 1;
    if (pdl) { cfg.attrs = &attr; cfg.numAttrs = 1; }
    cudaLaunchKernelExC(&cfg, fn, args);
}

extern "C" void kernel_launch(void* const* d_in, const int* in_sizes, int n_in,
                              void* d_out, int out_size) {
    const float* x  = (const float*)d_in[0];   // [N,5]
    const int*   ei = (const int*)d_in[1];     // [2,E] int32
    const float* W1 = (const float*)d_in[2];   // [5,16]
    const float* b1 = (const float*)d_in[3];   // [16]
    const float* W2 = (const float*)d_in[4];   // [16,4]
    const float* b2 = (const float*)d_in[5];   // [4]

    int n = in_sizes[0] / 5;
    int e = in_sizes[1] / 2;
    const int* src = ei;
    const int* dst = ei + e;

    float4* out = (float4*)d_out;

    const int BN = 256;   // node kernels
    const int BE = 64;    // edge kernels (empirical optimum of the block-size curve)
    int gn = (n + BN - 1) / BN;

    bool vec4 = ((e & 3) == 0) && ((((uintptr_t)dst) & 15) == 0) && ((((uintptr_t)src) & 15) == 0);
    int e4   = vec4 ? e / 4 : 0;
    int ge4  = (e4 + BE - 1) / BE;
    int gd   = ((e4 + 1) / 2 + BE - 1) / BE;
    int tail = e4 * 4;
    int gts  = (e - tail + BE - 1) / BE;

    const int4* src4 = (const int4*)src;
    const int4* dst4 = (const int4*)dst;

    if (vec4) {
        void* a[] = {(void*)&dst4, (void*)&e4};
        launch_k((const void*)k_deg_count, gd, BE, a, false);
    }
    if (tail < e) {
        void* a[] = {(void*)&dst, (void*)&tail, (void*)&e};
        launch_k((const void*)k_deg_scalar, gts, BE, a, vec4);
    }
    {   void* a[] = {(void*)&x, (void*)&n};
        launch_k((const void*)k_node1, gn, BN, a, true); }
    if (vec4) {
        void* a[] = {(void*)&src4, (void*)&dst4, (void*)&e4};
        launch_k((const void*)k_edge1, ge4, BE, a, true);
    }
    if (tail < e) {
        void* a[] = {(void*)&src, (void*)&dst, (void*)&tail, (void*)&e};
        launch_k((const void*)k_edge1_scalar, gts, BE, a, true);
    }
    {   void* a[] = {(void*)&W1, (void*)&b1, (void*)&W2, (void*)&out, (void*)&n};
        launch_k((const void*)k_node2, gn, BN, a, true); }
    if (vec4) {
        void* a[] = {(void*)&src4, (void*)&dst4, (void*)&out, (void*)&e4};
        launch_k((const void*)k_edge2, ge4, BE, a, true);
    }
    if (tail < e) {
        void* a[] = {(void*)&src, (void*)&dst, (void*)&out, (void*)&tail, (void*)&e};
        launch_k((const void*)k_edge2_scalar, gts, BE, a, true);
    }
    {   void* a[] = {(void*)&b2, (void*)&out, (void*)&n};
        launch_k((const void*)k_node3, gn, BN, a, true); }
}